// round 2
// baseline (speedup 1.0000x reference)
#include <cuda_runtime.h>

// Problem constants
#define BATCH 4
#define SEQ   2048
#define CH    1024
#define HEADS 16
#define HD    64
#define MTOT  (BATCH * SEQ)   // 8192
#define SCALE 0.125f          // HD^-0.5

// Scratch (allocation-free: __device__ globals)
__device__ float g_q[BATCH * HEADS * SEQ * HD];   // [bh][n][hd]
__device__ float g_k[BATCH * HEADS * SEQ * HD];
__device__ float g_v[BATCH * HEADS * SEQ * HD];
__device__ float g_ao[BATCH * SEQ * CH];          // attention output [b*N+n][c]

// ----------------------------------------------------------------------------
// Kernel 1: QKV projection.  out[m][d] = sum_c X[m][c] * W[d][c]
// M=8192, Nd=3072, K=1024.  Tile 64x64x16, 256 threads, 4x4 microtile.
// Epilogue scatters into g_q/g_k/g_v with [b*H+h][n][hd] layout.
// ----------------------------------------------------------------------------
__global__ __launch_bounds__(256) void qkv_gemm(const float* __restrict__ X,
                                                const float* __restrict__ W) {
    __shared__ float Xs[64 * 17];
    __shared__ float Ws[64 * 17];

    const int tid = threadIdx.x;
    const int ty = tid >> 4, tx = tid & 15;
    const int m0 = blockIdx.y * 64;
    const int n0 = blockIdx.x * 64;

    const int lr = tid >> 2;          // 0..63
    const int lc = (tid & 3) << 2;    // 0,4,8,12

    float acc[4][4] = {};

    for (int k0 = 0; k0 < 1024; k0 += 16) {
        __syncthreads();
        float4 xa = *(const float4*)(X + (size_t)(m0 + lr) * 1024 + k0 + lc);
        float4 wa = *(const float4*)(W + (size_t)(n0 + lr) * 1024 + k0 + lc);
        float* xp = Xs + lr * 17 + lc;
        xp[0] = xa.x; xp[1] = xa.y; xp[2] = xa.z; xp[3] = xa.w;
        float* wp = Ws + lr * 17 + lc;
        wp[0] = wa.x; wp[1] = wa.y; wp[2] = wa.z; wp[3] = wa.w;
        __syncthreads();

#pragma unroll
        for (int kk = 0; kk < 16; kk++) {
            float a[4], b[4];
#pragma unroll
            for (int i = 0; i < 4; i++) a[i] = Xs[(4 * ty + i) * 17 + kk];
#pragma unroll
            for (int j = 0; j < 4; j++) b[j] = Ws[(4 * tx + j) * 17 + kk];
#pragma unroll
            for (int i = 0; i < 4; i++)
#pragma unroll
                for (int j = 0; j < 4; j++) acc[i][j] += a[i] * b[j];
        }
    }

    // Scatter: d = n0 + 4*tx + j ;  d -> (three, h, hd). n0 multiple of 64 so
    // the whole 64-wide tile lies in one (three, h).
    const int three = n0 >> 10;
    const int h = (n0 >> 6) & 15;
    float* dst = (three == 0) ? g_q : (three == 1) ? g_k : g_v;
#pragma unroll
    for (int i = 0; i < 4; i++) {
        int m = m0 + 4 * ty + i;
        int b_ = m >> 11;          // /2048
        int n_ = m & 2047;
        float4 v4 = make_float4(acc[i][0], acc[i][1], acc[i][2], acc[i][3]);
        *(float4*)(dst + (size_t)((b_ * 16 + h) * 2048 + n_) * 64 + 4 * tx) = v4;
    }
}

// ----------------------------------------------------------------------------
// Kernel 2: flash attention.  One block per (b,h, 64-query tile).
// BM=BN=64, online softmax, bias[k] = mWin[b,k]*100 - 100 (key-only).
// P is staged into the K smem buffer for the PV pass.
// ----------------------------------------------------------------------------
__global__ __launch_bounds__(256) void attn_kernel(const float* __restrict__ mWin) {
    extern __shared__ float sm[];
    float* Qs     = sm;            // [64][65]  (Q * SCALE)
    float* Ks     = sm + 4160;     // [64][65]  (K tile, then P tile)
    float* Vs     = sm + 8320;     // [64][64]
    float* bias_s = sm + 12416;    // [64]

    const int tid = threadIdx.x;
    const int ty = tid >> 4, tx = tid & 15;
    const int qt = blockIdx.x & 31;     // query tile 0..31
    const int bh = blockIdx.x >> 5;     // 0..63
    const int b  = bh >> 4;
    const int h  = bh & 15;

    const float* qg  = g_q + (size_t)(bh * 2048 + qt * 64) * 64;
    const float* kg0 = g_k + (size_t)bh * 2048 * 64;
    const float* vg0 = g_v + (size_t)bh * 2048 * 64;

    // Stage Q (scaled) with pad-65 rows
    for (int i = tid; i < 1024; i += 256) {
        int r = i >> 4, c = (i & 15) << 2;
        float4 v = *(const float4*)(qg + r * 64 + c);
        float* p = Qs + r * 65 + c;
        p[0] = v.x * SCALE; p[1] = v.y * SCALE; p[2] = v.z * SCALE; p[3] = v.w * SCALE;
    }

    float acc[4][4] = {};
    float mrow[4] = {-1e30f, -1e30f, -1e30f, -1e30f};
    float lrow[4] = {};

    for (int kt = 0; kt < 32; kt++) {
        __syncthreads();   // prior PV reads (and Q staging, iter 0) complete

        const float* kg = kg0 + kt * 64 * 64;
        const float* vg = vg0 + kt * 64 * 64;
        for (int i = tid; i < 1024; i += 256) {
            int r = i >> 4, c = (i & 15) << 2;
            float4 v = *(const float4*)(kg + r * 64 + c);
            float* p = Ks + r * 65 + c;
            p[0] = v.x; p[1] = v.y; p[2] = v.z; p[3] = v.w;
            *(float4*)(Vs + r * 64 + c) = *(const float4*)(vg + r * 64 + c);
        }
        if (tid < 64) bias_s[tid] = mWin[b * 2048 + kt * 64 + tid] * 100.0f - 100.0f;
        __syncthreads();

        // S = (Q*SCALE) K^T  (64x64x64)
        float s[4][4] = {};
#pragma unroll 8
        for (int d = 0; d < 64; d++) {
            float a[4], kv[4];
#pragma unroll
            for (int i = 0; i < 4; i++) a[i] = Qs[(4 * ty + i) * 65 + d];
#pragma unroll
            for (int j = 0; j < 4; j++) kv[j] = Ks[(4 * tx + j) * 65 + d];
#pragma unroll
            for (int i = 0; i < 4; i++)
#pragma unroll
                for (int j = 0; j < 4; j++) s[i][j] += a[i] * kv[j];
        }

        float bj[4];
#pragma unroll
        for (int j = 0; j < 4; j++) bj[j] = bias_s[4 * tx + j];
#pragma unroll
        for (int i = 0; i < 4; i++)
#pragma unroll
            for (int j = 0; j < 4; j++) s[i][j] += bj[j];

        // Online softmax per row (rows owned by ty-group; reduce across 16 tx lanes)
#pragma unroll
        for (int i = 0; i < 4; i++) {
            float mloc = fmaxf(fmaxf(s[i][0], s[i][1]), fmaxf(s[i][2], s[i][3]));
#pragma unroll
            for (int off = 8; off >= 1; off >>= 1)
                mloc = fmaxf(mloc, __shfl_xor_sync(0xffffffffu, mloc, off));
            float mnew = fmaxf(mrow[i], mloc);
            float corr = __expf(mrow[i] - mnew);
            float ls = 0.0f;
#pragma unroll
            for (int j = 0; j < 4; j++) {
                s[i][j] = __expf(s[i][j] - mnew);
                ls += s[i][j];
            }
#pragma unroll
            for (int off = 8; off >= 1; off >>= 1)
                ls += __shfl_xor_sync(0xffffffffu, ls, off);
            lrow[i] = lrow[i] * corr + ls;
            mrow[i] = mnew;
#pragma unroll
            for (int j = 0; j < 4; j++) acc[i][j] *= corr;
        }

        __syncthreads();   // everyone done reading Ks as K
        // Stage P into Ks buffer: Ps[row][key], stride 65
#pragma unroll
        for (int i = 0; i < 4; i++)
#pragma unroll
            for (int j = 0; j < 4; j++)
                Ks[(4 * ty + i) * 65 + 4 * tx + j] = s[i][j];
        __syncthreads();

        // O += P V  (64x64x64)
#pragma unroll 8
        for (int k = 0; k < 64; k++) {
            float pv[4], vv[4];
#pragma unroll
            for (int i = 0; i < 4; i++) pv[i] = Ks[(4 * ty + i) * 65 + k];
#pragma unroll
            for (int j = 0; j < 4; j++) vv[j] = Vs[k * 64 + 4 * tx + j];
#pragma unroll
            for (int i = 0; i < 4; i++)
#pragma unroll
                for (int j = 0; j < 4; j++) acc[i][j] += pv[i] * vv[j];
        }
    }

    // Epilogue: divide by l, write [b*N+n][h*64+hd]
    const int qbase = b * 2048 + qt * 64;
#pragma unroll
    for (int i = 0; i < 4; i++) {
        float inv = 1.0f / lrow[i];
        float4 o = make_float4(acc[i][0] * inv, acc[i][1] * inv,
                               acc[i][2] * inv, acc[i][3] * inv);
        *(float4*)(g_ao + (size_t)(qbase + 4 * ty + i) * 1024 + h * 64 + 4 * tx) = o;
    }
}

// ----------------------------------------------------------------------------
// Kernel 3: output projection.  out[m][d] = sum_c g_ao[m][c]*Wp[d][c] + bias[d]
// ----------------------------------------------------------------------------
__global__ __launch_bounds__(256) void proj_gemm(const float* __restrict__ W,
                                                 const float* __restrict__ bias,
                                                 float* __restrict__ out) {
    __shared__ float Xs[64 * 17];
    __shared__ float Ws[64 * 17];

    const int tid = threadIdx.x;
    const int ty = tid >> 4, tx = tid & 15;
    const int m0 = blockIdx.y * 64;
    const int n0 = blockIdx.x * 64;

    const int lr = tid >> 2;
    const int lc = (tid & 3) << 2;

    float acc[4][4] = {};

    for (int k0 = 0; k0 < 1024; k0 += 16) {
        __syncthreads();
        float4 xa = *(const float4*)(g_ao + (size_t)(m0 + lr) * 1024 + k0 + lc);
        float4 wa = *(const float4*)(W + (size_t)(n0 + lr) * 1024 + k0 + lc);
        float* xp = Xs + lr * 17 + lc;
        xp[0] = xa.x; xp[1] = xa.y; xp[2] = xa.z; xp[3] = xa.w;
        float* wp = Ws + lr * 17 + lc;
        wp[0] = wa.x; wp[1] = wa.y; wp[2] = wa.z; wp[3] = wa.w;
        __syncthreads();

#pragma unroll
        for (int kk = 0; kk < 16; kk++) {
            float a[4], b[4];
#pragma unroll
            for (int i = 0; i < 4; i++) a[i] = Xs[(4 * ty + i) * 17 + kk];
#pragma unroll
            for (int j = 0; j < 4; j++) b[j] = Ws[(4 * tx + j) * 17 + kk];
#pragma unroll
            for (int i = 0; i < 4; i++)
#pragma unroll
                for (int j = 0; j < 4; j++) acc[i][j] += a[i] * b[j];
        }
    }

    float4 bv = *(const float4*)(bias + n0 + 4 * tx);
#pragma unroll
    for (int i = 0; i < 4; i++) {
        int m = m0 + 4 * ty + i;
        float4 o = make_float4(acc[i][0] + bv.x, acc[i][1] + bv.y,
                               acc[i][2] + bv.z, acc[i][3] + bv.w);
        *(float4*)(out + (size_t)m * 1024 + n0 + 4 * tx) = o;
    }
}

// ----------------------------------------------------------------------------
extern "C" void kernel_launch(void* const* d_in, const int* in_sizes, int n_in,
                              void* d_out, int out_size) {
    const float* x      = (const float*)d_in[0];
    const float* mWin   = (const float*)d_in[1];
    const float* w_qkv  = (const float*)d_in[2];
    const float* w_proj = (const float*)d_in[3];
    const float* b_proj = (const float*)d_in[4];
    float* out = (float*)d_out;

    const int ATTN_SMEM = 49920;  // (4160+4160+4096+64) floats
    cudaFuncSetAttribute(attn_kernel, cudaFuncAttributeMaxDynamicSharedMemorySize,
                         ATTN_SMEM);

    qkv_gemm<<<dim3(48, 128), 256>>>(x, w_qkv);
    attn_kernel<<<2048, 256, ATTN_SMEM>>>(mWin);
    proj_gemm<<<dim3(16, 128), 256>>>(w_proj, b_proj, out);
}